// round 8
// baseline (speedup 1.0000x reference)
#include <cuda_runtime.h>
#include <stdint.h>

typedef unsigned long long u64;

#define M_UP   32768
#define N_DOWN 8192
#define C_OUT  128

#define GRID   32
#define NC     (GRID*GRID*GRID)
#define NEDGE  31

#define SKEW(i) ((i) + ((i) >> 5))
#define SCAN_SMEM_INTS (SKEW(NC) + 32 + 1024)
#define SCAN_SMEM_BYTES (SCAN_SMEM_INTS * 4)

#define QPB 64   // queries per knn block (x4 splits = 256 threads)

// standard-normal quantiles Phi^-1(i/32), i=1..31 (monotone edges; exactness
// of the quantile values is irrelevant to correctness, only to balance)
__device__ __constant__ float c_edge[NEDGE] = {
    -1.8627f, -1.5341f, -1.3180f, -1.1503f, -1.0100f, -0.8871f, -0.7764f,
    -0.6745f, -0.5791f, -0.4888f, -0.4023f, -0.3186f, -0.2372f, -0.1573f,
    -0.0784f,  0.0000f,  0.0784f,  0.1573f,  0.2372f,  0.3186f,  0.4023f,
     0.4888f,  0.5791f,  0.6745f,  0.7764f,  0.8871f,  1.0100f,  1.1503f,
     1.3180f,  1.5341f,  1.8627f };

// ---------------- device scratch (no allocations allowed) ----------------
__device__ int   g_cellcnt[NC];        // zero-initialized at load; re-zeroed by lin_up
__device__ int   g_qcnt[NC];           // "
__device__ int   g_cellstart[NC + 1];
__device__ int   g_cellcur[NC];
__device__ int   g_qcur[NC];
__device__ __align__(16) float4 g_spts[N_DOWN];   // sorted points {x,y,z,|p|^2}
__device__ int   g_ptid[N_DOWN];                  // sorted pos -> original idx
__device__ int   g_qorder[M_UP];                  // sorted pos -> query idx
__device__ float g_downf[N_DOWN * C_OUT];
__device__ int   g_knn_idx[3][M_UP];
__device__ float g_knn_w[3][M_UP];

// ---------------- f32x2 helpers (sm_103a packed fp32) ----------------
__device__ __forceinline__ void fma2(u64& d, u64 a, u64 b) {
    asm("fma.rn.f32x2 %0, %1, %2, %0;" : "+l"(d) : "l"(a), "l"(b));
}
__device__ __forceinline__ u64 splat2(float s) {
    u64 d; unsigned int b = __float_as_uint(s);
    asm("mov.b64 %0, {%1, %1};" : "=l"(d) : "r"(b));
    return d;
}
union U64F2 { u64 u; float2 f; };

// ---------------- warped-grid binning: 31 unrolled compares ----------------
__device__ __forceinline__ int cell_coord(float x) {
    int c = 0;
    #pragma unroll
    for (int j = 0; j < NEDGE; j++) c += (x >= c_edge[j]);
    return c;          // 0..31
}
__device__ __forceinline__ unsigned mexpand5(unsigned v) {
    v &= 0x1F;
    v = (v | (v << 8)) & 0x100F;
    v = (v | (v << 4)) & 0x10C3;
    v = (v | (v << 2)) & 0x1249;
    return v;
}
__device__ __forceinline__ int morton3(int x, int y, int z) {
    return (int)(mexpand5(x) | (mexpand5(y) << 1) | (mexpand5(z) << 2));
}

// branchless top-3 insert (pred-as-data SELs, no BSSY)
__device__ __forceinline__ void bins3(float s, int p,
                                      float& s0, float& s1, float& s2,
                                      int& i0, int& i1, int& i2) {
    bool b0 = s < s0, b1 = s < s1, b2 = s < s2;
    float ns2 = b1 ? s1 : (b2 ? s : s2);
    int   ni2 = b1 ? i1 : (b2 ? p : i2);
    float ns1 = b0 ? s0 : (b1 ? s : s1);
    int   ni1 = b0 ? i0 : (b1 ? p : i1);
    s0 = b0 ? s : s0;  i0 = b0 ? p : i0;
    s1 = ns1; i1 = ni1; s2 = ns2; i2 = ni2;
}

// ---------------- histogram ----------------
__global__ void hist_kernel(const float* __restrict__ dp,
                            const float* __restrict__ qp) {
    int i = blockIdx.x * blockDim.x + threadIdx.x;
    if (i < N_DOWN) {
        int cx = cell_coord(dp[3*i]), cy = cell_coord(dp[3*i+1]), cz = cell_coord(dp[3*i+2]);
        atomicAdd(&g_cellcnt[(cz * GRID + cy) * GRID + cx], 1);
    } else if (i < N_DOWN + M_UP) {
        int m = i - N_DOWN;
        int cx = cell_coord(qp[3*m]), cy = cell_coord(qp[3*m+1]), cz = cell_coord(qp[3*m+2]);
        atomicAdd(&g_qcnt[morton3(cx, cy, cz)], 1);
    }
}

// one block, 1024 threads: exclusive scan of both count arrays (coalesced staging)
__global__ void __launch_bounds__(1024) scan_kernel() {
    extern __shared__ int dsh[];
    int* tile = dsh;
    int* bsum = dsh + SKEW(NC) + 32;
    const int t = threadIdx.x;
    const int base = t * 32;

    #pragma unroll 1
    for (int pass = 0; pass < 2; pass++) {
        const int* src = pass ? g_qcnt : g_cellcnt;
        for (int j = t; j < NC; j += 1024) tile[SKEW(j)] = src[j];
        __syncthreads();

        int loc[32]; int s = 0;
        #pragma unroll
        for (int i = 0; i < 32; i++) { loc[i] = s; s += tile[SKEW(base + i)]; }
        bsum[t] = s;
        __syncthreads();
        for (int d = 1; d < 1024; d <<= 1) {
            int a = (t >= d) ? bsum[t - d] : 0;
            __syncthreads();
            bsum[t] += a;
            __syncthreads();
        }
        int off = bsum[t] - s;
        #pragma unroll
        for (int i = 0; i < 32; i++) tile[SKEW(base + i)] = off + loc[i];
        __syncthreads();

        if (pass == 0) {
            for (int j = t; j < NC; j += 1024) {
                int v = tile[SKEW(j)];
                g_cellstart[j] = v;
                g_cellcur[j]   = v;
            }
            if (t == 1023) g_cellstart[NC] = off + s;
        } else {
            for (int j = t; j < NC; j += 1024) g_qcur[j] = tile[SKEW(j)];
        }
        __syncthreads();
    }
}

__global__ void scatter_kernel(const float* __restrict__ dp,
                               const float* __restrict__ qp) {
    int i = blockIdx.x * blockDim.x + threadIdx.x;
    if (i < N_DOWN) {
        float x = dp[3*i], y = dp[3*i+1], z = dp[3*i+2];
        int cx = cell_coord(x), cy = cell_coord(y), cz = cell_coord(z);
        int pos = atomicAdd(&g_cellcur[(cz * GRID + cy) * GRID + cx], 1);
        g_spts[pos] = make_float4(x, y, z, fmaf(x, x, fmaf(y, y, z * z)));
        g_ptid[pos] = i;
    } else if (i < N_DOWN + M_UP) {
        int m = i - N_DOWN;
        int cx = cell_coord(qp[3*m]), cy = cell_coord(qp[3*m+1]), cz = cell_coord(qp[3*m+2]);
        int pos = atomicAdd(&g_qcur[morton3(cx, cy, cz)], 1);
        g_qorder[pos] = m;
    }
}

// ---------------- exact KNN: 4 lanes/query in one warp, rings in lockstep ----
// lane = qsub*4 + split; splits partition rows by (z&1, y&1) parity.
// Per ring, a 4-lane shfl butterfly shares min(partial s2) -> tight exact stop.
__global__ void __launch_bounds__(256) knn_grid_kernel(const float* __restrict__ qp) {
    __shared__ float se[NEDGE];
    const int tl   = threadIdx.x;
    if (tl < NEDGE) se[tl] = c_edge[tl];
    __syncthreads();

    const int lane  = tl & 31;
    const int warp  = tl >> 5;
    const int split = lane & 3;
    const int qsub  = lane >> 2;
    const int sz    = split & 1;
    const int sy    = split >> 1;
    const unsigned gmask = 0xFu << (lane & 28);

    const int t = blockIdx.x * QPB + warp * 8 + qsub;
    const int m = g_qorder[t];

    const float qx = qp[3*m], qy = qp[3*m+1], qz = qp[3*m+2];
    const float qn = fmaf(qx, qx, fmaf(qy, qy, qz * qz));
    const int cx = cell_coord(qx), cy = cell_coord(qy), cz = cell_coord(qz);

    float s0 = 3e38f, s1 = 3e38f, s2 = 3e38f;   // s = |p|^2 - 2 q.p  (= d^2 - qn)
    int   i0 = 0,     i1 = 0,     i2 = 0;

    for (int R = 0; R < GRID; R++) {
        const int zlo = max(cz - R, 0), zhi = min(cz + R, GRID - 1);
        const int z0  = zlo + ((zlo ^ sz) & 1);
        for (int z = z0; z <= zhi; z += 2) {
            const bool zedge = (z == cz - R) || (z == cz + R);
            const int ylo = max(cy - R, 0), yhi = min(cy + R, GRID - 1);
            const int y0  = ylo + ((ylo ^ sy) & 1);
            for (int y = y0; y <= yhi; y += 2) {
                const bool yedge = (y == cy - R) || (y == cy + R);
                const int rowbase = (z * GRID + y) * GRID;
                if (zedge || yedge) {
                    const int xlo = max(cx - R, 0), xhi = min(cx + R, GRID - 1);
                    const int start = g_cellstart[rowbase + xlo];
                    const int end   = g_cellstart[rowbase + xhi + 1];
                    for (int p = start; p < end; p++) {
                        float4 P = g_spts[p];
                        float s = fmaf(-2.0f,
                                       fmaf(qx, P.x, fmaf(qy, P.y, qz * P.z)), P.w);
                        bins3(s, p, s0, s1, s2, i0, i1, i2);
                    }
                } else {
                    #pragma unroll
                    for (int side = 0; side < 2; side++) {
                        int xc = side ? cx + R : cx - R;
                        if (xc < 0 || xc > GRID - 1) continue;
                        const int start = g_cellstart[rowbase + xc];
                        const int end   = g_cellstart[rowbase + xc + 1];
                        for (int p = start; p < end; p++) {
                            float4 P = g_spts[p];
                            float s = fmaf(-2.0f,
                                           fmaf(qx, P.x, fmaf(qy, P.y, qz * P.z)), P.w);
                            bins3(s, p, s0, s1, s2, i0, i1, i2);
                        }
                    }
                }
            }
        }
        // group-shared stop bound: min over splits of partial s2 (>= global s2)
        float s2m = s2;
        s2m = fminf(s2m, __shfl_xor_sync(gmask, s2m, 1));
        s2m = fminf(s2m, __shfl_xor_sync(gmask, s2m, 2));
        // exact Euclidean distance from q to nearest face of the scanned box
        float mind = 3e38f;
        if (cx - R >= 1)        mind = fminf(mind, qx - se[cx - R - 1]);
        if (cx + R <= GRID - 2) mind = fminf(mind, se[cx + R] - qx);
        if (cy - R >= 1)        mind = fminf(mind, qy - se[cy - R - 1]);
        if (cy + R <= GRID - 2) mind = fminf(mind, se[cy + R] - qy);
        if (cz - R >= 1)        mind = fminf(mind, qz - se[cz - R - 1]);
        if (cz + R <= GRID - 2) mind = fminf(mind, se[cz + R] - qz);
        if (fmaf(mind, mind, -qn) >= s2m) break;   // group-uniform decision
    }

    // merge 4 splits via shfl butterfly (all lanes converge per group)
    #pragma unroll
    for (int off = 1; off <= 2; off <<= 1) {
        float t0 = __shfl_xor_sync(gmask, s0, off);
        float t1 = __shfl_xor_sync(gmask, s1, off);
        float t2 = __shfl_xor_sync(gmask, s2, off);
        int   u0 = __shfl_xor_sync(gmask, i0, off);
        int   u1 = __shfl_xor_sync(gmask, i1, off);
        int   u2 = __shfl_xor_sync(gmask, i2, off);
        bins3(t0, u0, s0, s1, s2, i0, i1, i2);
        bins3(t1, u1, s0, s1, s2, i0, i1, i2);
        bins3(t2, u2, s0, s1, s2, i0, i1, i2);
    }

    if (split == 0) {
        float d0 = fmaxf(s0 + qn, 0.0f);
        float d1 = fmaxf(s1 + qn, 0.0f);
        float d2 = fmaxf(s2 + qn, 0.0f);
        float r0 = 1.0f / (d0 + 1e-8f);
        float r1 = 1.0f / (d1 + 1e-8f);
        float r2 = 1.0f / (d2 + 1e-8f);
        float inv = 1.0f / (r0 + r1 + r2);
        g_knn_idx[0][m] = g_ptid[i0];
        g_knn_idx[1][m] = g_ptid[i1];
        g_knn_idx[2][m] = g_ptid[i2];
        g_knn_w[0][m] = r0 * inv;
        g_knn_w[1][m] = r1 * inv;
        g_knn_w[2][m] = r2 * inv;
    }
}

// ---------------- fp32 linear: out[M][128] = A[M][KTOT] @ W[128][KTOT]^T + b ----
// FUSE also re-zeros the grid count arrays for the next replay.
template<int BM, int KTOT, bool FUSE>
__global__ void __launch_bounds__(BM*2) linear_kernel(
    const float* __restrict__ A,
    const float* __restrict__ W,
    const float* __restrict__ bias,
    float* __restrict__ out)
{
    constexpr int BK   = 32;
    constexpr int NT   = BM * 2;
    constexpr int ASTR = BM + 4;
    __shared__ __align__(16) float As[BK][ASTR];
    __shared__ __align__(16) float Ws[BK][C_OUT + 4];

    const int tid = threadIdx.x;
    const int tx  = tid & 15;
    const int ty  = tid >> 4;
    const int rowBase = blockIdx.x * BM;

    if (FUSE) {
        int g = blockIdx.x * NT + tid;
        if (g < NC) { g_cellcnt[g] = 0; g_qcnt[g] = 0; }
    }

    u64 acc[8][4];
    #pragma unroll
    for (int i = 0; i < 8; i++)
        #pragma unroll
        for (int j = 0; j < 4; j++) acc[i][j] = 0ull;

    for (int k0 = 0; k0 < KTOT; k0 += BK) {
        #pragma unroll
        for (int i = tid; i < BM * (BK/4); i += NT) {
            int r  = i >> 3;
            int kq = (i & 7) << 2;
            float4 v = *(const float4*)(A + (size_t)(rowBase + r) * KTOT + k0 + kq);
            As[kq+0][r] = v.x; As[kq+1][r] = v.y; As[kq+2][r] = v.z; As[kq+3][r] = v.w;
        }
        #pragma unroll
        for (int i = tid; i < C_OUT * (BK/4); i += NT) {
            int c  = i >> 3;
            int kq = (i & 7) << 2;
            float4 v = *(const float4*)(W + (size_t)c * KTOT + k0 + kq);
            Ws[kq+0][c] = v.x; Ws[kq+1][c] = v.y; Ws[kq+2][c] = v.z; Ws[kq+3][c] = v.w;
        }
        __syncthreads();
        #pragma unroll
        for (int k = 0; k < BK; k++) {
            float4 alo = *(const float4*)&As[k][ty*8];
            float4 ahi = *(const float4*)&As[k][ty*8 + 4];
            ulonglong2 w01 = *(const ulonglong2*)&Ws[k][tx*8];
            ulonglong2 w23 = *(const ulonglong2*)&Ws[k][tx*8 + 4];
            u64 wv[4] = {w01.x, w01.y, w23.x, w23.y};
            u64 a2[8];
            a2[0] = splat2(alo.x); a2[1] = splat2(alo.y);
            a2[2] = splat2(alo.z); a2[3] = splat2(alo.w);
            a2[4] = splat2(ahi.x); a2[5] = splat2(ahi.y);
            a2[6] = splat2(ahi.z); a2[7] = splat2(ahi.w);
            #pragma unroll
            for (int i = 0; i < 8; i++)
                #pragma unroll
                for (int j = 0; j < 4; j++)
                    fma2(acc[i][j], a2[i], wv[j]);
        }
        __syncthreads();
    }

    const int cb = tx * 8;
    float b[8];
    #pragma unroll
    for (int j = 0; j < 8; j++) b[j] = bias[cb + j];

    #pragma unroll
    for (int i = 0; i < 8; i++) {
        const int m = rowBase + ty*8 + i;
        float o[8];
        #pragma unroll
        for (int j = 0; j < 4; j++) {
            U64F2 cvt; cvt.u = acc[i][j];
            o[2*j]   = cvt.f.x + b[2*j];
            o[2*j+1] = cvt.f.y + b[2*j+1];
        }
        if (FUSE) {
            #pragma unroll
            for (int t = 0; t < 3; t++) {
                int   idx = g_knn_idx[t][m];
                float w   = g_knn_w[t][m];
                const float* fr = g_downf + (size_t)idx * C_OUT + cb;
                float4 glo = *(const float4*)fr;
                float4 ghi = *(const float4*)(fr + 4);
                o[0] = fmaf(w, glo.x, o[0]); o[1] = fmaf(w, glo.y, o[1]);
                o[2] = fmaf(w, glo.z, o[2]); o[3] = fmaf(w, glo.w, o[3]);
                o[4] = fmaf(w, ghi.x, o[4]); o[5] = fmaf(w, ghi.y, o[5]);
                o[6] = fmaf(w, ghi.z, o[6]); o[7] = fmaf(w, ghi.w, o[7]);
            }
        }
        *(float4*)(out + (size_t)m * C_OUT + cb)     = make_float4(o[0], o[1], o[2], o[3]);
        *(float4*)(out + (size_t)m * C_OUT + cb + 4) = make_float4(o[4], o[5], o[6], o[7]);
    }
}

// ---------------- launch (ncu profiles launch #4 = knn_grid) ----------------
extern "C" void kernel_launch(void* const* d_in, const int* in_sizes, int n_in,
                              void* d_out, int out_size) {
    (void)in_sizes; (void)n_in; (void)out_size;
    const float* up_points     = (const float*)d_in[0];
    const float* up_features   = (const float*)d_in[1];
    const float* down_points   = (const float*)d_in[2];
    const float* down_features = (const float*)d_in[3];
    const float* W_up          = (const float*)d_in[4];
    const float* b_up          = (const float*)d_in[5];
    const float* W_down        = (const float*)d_in[6];
    const float* b_down        = (const float*)d_in[7];
    float* out = (float*)d_out;

    float* downf_ptr = nullptr;
    cudaGetSymbolAddress((void**)&downf_ptr, g_downf);
    cudaFuncSetAttribute(scan_kernel, cudaFuncAttributeMaxDynamicSharedMemorySize,
                         SCAN_SMEM_BYTES);

    hist_kernel<<<(N_DOWN + M_UP + 255) / 256, 256>>>(down_points, up_points);      // 1
    scan_kernel<<<1, 1024, SCAN_SMEM_BYTES>>>();                                     // 2
    scatter_kernel<<<(N_DOWN + M_UP + 255) / 256, 256>>>(down_points, up_points);    // 3
    knn_grid_kernel<<<M_UP / QPB, 256>>>(up_points);                                 // 4 <- profiled
    linear_kernel<64, 256, false><<<N_DOWN / 64, 128>>>(down_features, W_down, b_down, downf_ptr); // 5
    linear_kernel<64, 128, true><<<M_UP / 64, 128>>>(up_features, W_up, b_up, out);  // 6
}

// round 9
// speedup vs baseline: 3.5744x; 3.5744x over previous
#include <cuda_runtime.h>
#include <stdint.h>

typedef unsigned long long u64;

#define M_UP   32768
#define N_DOWN 8192
#define C_OUT  128

#define GRID   32
#define NC     (GRID*GRID*GRID)
#define LOC    (-4.25f)
#define CELLH  (8.5f / GRID)
#define INVH   ((float)GRID / 8.5f)

#define SKEW(i) ((i) + ((i) >> 5))
#define SCAN_SMEM_INTS (SKEW(NC) + 32 + 1024)
#define SCAN_SMEM_BYTES (SCAN_SMEM_INTS * 4)

#define QPB 32   // queries per knn block (x4 splits = 128 threads)

// ---------------- device scratch (no allocations allowed) ----------------
__device__ int   g_cellcnt[NC];        // zero-initialized at load; re-zeroed by lin_up
__device__ int   g_qcnt[NC];           // "
__device__ int   g_cellstart[NC + 1];
__device__ int   g_cellcur[NC];
__device__ int   g_qcur[NC];
__device__ __align__(16) float4 g_spts[N_DOWN];   // sorted points {x,y,z,|p|^2}
__device__ int   g_ptid[N_DOWN];                  // sorted pos -> original idx
__device__ int   g_qorder[M_UP];                  // sorted pos -> query idx
__device__ float g_downf[N_DOWN * C_OUT];
__device__ int   g_knn_idx[3][M_UP];
__device__ float g_knn_w[3][M_UP];

// ---------------- f32x2 helpers (sm_103a packed fp32) ----------------
__device__ __forceinline__ void fma2(u64& d, u64 a, u64 b) {
    asm("fma.rn.f32x2 %0, %1, %2, %0;" : "+l"(d) : "l"(a), "l"(b));
}
__device__ __forceinline__ u64 splat2(float s) {
    u64 d; unsigned int b = __float_as_uint(s);
    asm("mov.b64 %0, {%1, %1};" : "=l"(d) : "r"(b));
    return d;
}
union U64F2 { u64 u; float2 f; };

// ---------------- uniform grid helpers ----------------
__device__ __forceinline__ int clampi(int v, int lo, int hi) {
    return v < lo ? lo : (v > hi ? hi : v);
}
__device__ __forceinline__ int cell_coord(float x) {
    return clampi((int)floorf((x - LOC) * INVH), 0, GRID - 1);
}
__device__ __forceinline__ unsigned mexpand5(unsigned v) {
    v &= 0x1F;
    v = (v | (v << 8)) & 0x100F;
    v = (v | (v << 4)) & 0x10C3;
    v = (v | (v << 2)) & 0x1249;
    return v;
}
__device__ __forceinline__ int morton3(int x, int y, int z) {
    return (int)(mexpand5(x) | (mexpand5(y) << 1) | (mexpand5(z) << 2));
}

// branchless top-3 insert (used only on the rare guarded hit + merges)
__device__ __forceinline__ void bins3(float s, int p,
                                      float& s0, float& s1, float& s2,
                                      int& i0, int& i1, int& i2) {
    bool b0 = s < s0, b1 = s < s1, b2 = s < s2;
    float ns2 = b1 ? s1 : (b2 ? s : s2);
    int   ni2 = b1 ? i1 : (b2 ? p : i2);
    float ns1 = b0 ? s0 : (b1 ? s : s1);
    int   ni1 = b0 ? i0 : (b1 ? p : i1);
    s0 = b0 ? s : s0;  i0 = b0 ? p : i0;
    s1 = ns1; i1 = ni1; s2 = ns2; i2 = ni2;
}

// ---------------- histogram ----------------
__global__ void hist_kernel(const float* __restrict__ dp,
                            const float* __restrict__ qp) {
    int i = blockIdx.x * blockDim.x + threadIdx.x;
    if (i < N_DOWN) {
        int cx = cell_coord(dp[3*i]), cy = cell_coord(dp[3*i+1]), cz = cell_coord(dp[3*i+2]);
        atomicAdd(&g_cellcnt[(cz * GRID + cy) * GRID + cx], 1);
    } else if (i < N_DOWN + M_UP) {
        int m = i - N_DOWN;
        int cx = cell_coord(qp[3*m]), cy = cell_coord(qp[3*m+1]), cz = cell_coord(qp[3*m+2]);
        atomicAdd(&g_qcnt[morton3(cx, cy, cz)], 1);
    }
}

// one block, 1024 threads: exclusive scan of both count arrays (coalesced staging)
__global__ void __launch_bounds__(1024) scan_kernel() {
    extern __shared__ int dsh[];
    int* tile = dsh;
    int* bsum = dsh + SKEW(NC) + 32;
    const int t = threadIdx.x;
    const int base = t * 32;

    #pragma unroll 1
    for (int pass = 0; pass < 2; pass++) {
        const int* src = pass ? g_qcnt : g_cellcnt;
        for (int j = t; j < NC; j += 1024) tile[SKEW(j)] = src[j];
        __syncthreads();

        int loc[32]; int s = 0;
        #pragma unroll
        for (int i = 0; i < 32; i++) { loc[i] = s; s += tile[SKEW(base + i)]; }
        bsum[t] = s;
        __syncthreads();
        for (int d = 1; d < 1024; d <<= 1) {
            int a = (t >= d) ? bsum[t - d] : 0;
            __syncthreads();
            bsum[t] += a;
            __syncthreads();
        }
        int off = bsum[t] - s;
        #pragma unroll
        for (int i = 0; i < 32; i++) tile[SKEW(base + i)] = off + loc[i];
        __syncthreads();

        if (pass == 0) {
            for (int j = t; j < NC; j += 1024) {
                int v = tile[SKEW(j)];
                g_cellstart[j] = v;
                g_cellcur[j]   = v;
            }
            if (t == 1023) g_cellstart[NC] = off + s;
        } else {
            for (int j = t; j < NC; j += 1024) g_qcur[j] = tile[SKEW(j)];
        }
        __syncthreads();
    }
}

__global__ void scatter_kernel(const float* __restrict__ dp,
                               const float* __restrict__ qp) {
    int i = blockIdx.x * blockDim.x + threadIdx.x;
    if (i < N_DOWN) {
        float x = dp[3*i], y = dp[3*i+1], z = dp[3*i+2];
        int cx = cell_coord(x), cy = cell_coord(y), cz = cell_coord(z);
        int pos = atomicAdd(&g_cellcur[(cz * GRID + cy) * GRID + cx], 1);
        g_spts[pos] = make_float4(x, y, z, fmaf(x, x, fmaf(y, y, z * z)));
        g_ptid[pos] = i;
    } else if (i < N_DOWN + M_UP) {
        int m = i - N_DOWN;
        int cx = cell_coord(qp[3*m]), cy = cell_coord(qp[3*m+1]), cz = cell_coord(qp[3*m+2]);
        int pos = atomicAdd(&g_qcur[morton3(cx, cy, cz)], 1);
        g_qorder[pos] = m;
    }
}

// ---------------- exact KNN (uniform grid): 4 lanes/query in one warp ----
// lane = qsub*4 + split; splits partition (z,y) rows by parity.
// Per ring a 2-shfl butterfly shares s2m = min(partial s2) -> tight exact stop.
__global__ void __launch_bounds__(128) knn_grid_kernel(const float* __restrict__ qp) {
    const int tl    = threadIdx.x;
    const int lane  = tl & 31;
    const int warp  = tl >> 5;
    const int split = lane & 3;
    const int qsub  = lane >> 2;
    const int sz    = split & 1;
    const int sy    = split >> 1;
    const unsigned gmask = 0xFu << (lane & 28);

    const int t = blockIdx.x * QPB + warp * 8 + qsub;
    const int m = g_qorder[t];

    const float qx = qp[3*m], qy = qp[3*m+1], qz = qp[3*m+2];
    const float qn = fmaf(qx, qx, fmaf(qy, qy, qz * qz));

    const int cx = cell_coord(qx), cy = cell_coord(qy), cz = cell_coord(qz);
    const float fx = qx - (LOC + cx * CELLH);
    const float fy = qy - (LOC + cy * CELLH);
    const float fz = qz - (LOC + cz * CELLH);
    const float gm = fmaxf(fmaxf(fmaxf(fx, CELLH - fx), fmaxf(fy, CELLH - fy)),
                           fmaxf(fz, CELLH - fz));

    float s0 = 3e38f, s1 = 3e38f, s2 = 3e38f;   // s = |p|^2 - 2 q.p  (= d^2 - qn)
    int   i0 = 0,     i1 = 0,     i2 = 0;

    for (int R = 0; R < GRID; R++) {
        const int zlo = max(cz - R, 0), zhi = min(cz + R, GRID - 1);
        const int z0  = zlo + ((zlo ^ sz) & 1);
        for (int z = z0; z <= zhi; z += 2) {
            const bool zedge = (z == cz - R) || (z == cz + R);
            const int ylo = max(cy - R, 0), yhi = min(cy + R, GRID - 1);
            const int y0  = ylo + ((ylo ^ sy) & 1);
            for (int y = y0; y <= yhi; y += 2) {
                const bool yedge = (y == cy - R) || (y == cy + R);
                const int rowbase = (z * GRID + y) * GRID;
                if (zedge || yedge) {
                    const int xlo = max(cx - R, 0), xhi = min(cx + R, GRID - 1);
                    const int start = g_cellstart[rowbase + xlo];
                    const int end   = g_cellstart[rowbase + xhi + 1];
                    for (int p = start; p < end; p++) {
                        float4 P = g_spts[p];
                        float s = fmaf(-2.0f,
                                       fmaf(qx, P.x, fmaf(qy, P.y, qz * P.z)), P.w);
                        if (s < s2)                       // rare
                            bins3(s, p, s0, s1, s2, i0, i1, i2);
                    }
                } else {
                    #pragma unroll
                    for (int side = 0; side < 2; side++) {
                        int xc = side ? cx + R : cx - R;
                        if (xc < 0 || xc > GRID - 1) continue;
                        const int start = g_cellstart[rowbase + xc];
                        const int end   = g_cellstart[rowbase + xc + 1];
                        for (int p = start; p < end; p++) {
                            float4 P = g_spts[p];
                            float s = fmaf(-2.0f,
                                           fmaf(qx, P.x, fmaf(qy, P.y, qz * P.z)), P.w);
                            if (s < s2)                   // rare
                                bins3(s, p, s0, s1, s2, i0, i1, i2);
                        }
                    }
                }
            }
        }
        // group-shared stop: s2m = min over splits of partial s2 (>= global s2,
        // so stopping on it is exact; tighter than each split's own s2)
        float s2m = s2;
        s2m = fminf(s2m, __shfl_xor_sync(gmask, s2m, 1));
        s2m = fminf(s2m, __shfl_xor_sync(gmask, s2m, 2));
        float mind = (float)(R + 1) * CELLH - gm;
        if (mind > 0.0f && fmaf(mind, mind, -qn) >= s2m) break;
    }

    // merge 4 splits via shfl butterfly (group-uniform)
    #pragma unroll
    for (int off = 1; off <= 2; off <<= 1) {
        float t0 = __shfl_xor_sync(gmask, s0, off);
        float t1 = __shfl_xor_sync(gmask, s1, off);
        float t2 = __shfl_xor_sync(gmask, s2, off);
        int   u0 = __shfl_xor_sync(gmask, i0, off);
        int   u1 = __shfl_xor_sync(gmask, i1, off);
        int   u2 = __shfl_xor_sync(gmask, i2, off);
        bins3(t0, u0, s0, s1, s2, i0, i1, i2);
        bins3(t1, u1, s0, s1, s2, i0, i1, i2);
        bins3(t2, u2, s0, s1, s2, i0, i1, i2);
    }

    if (split == 0) {
        float d0 = fmaxf(s0 + qn, 0.0f);
        float d1 = fmaxf(s1 + qn, 0.0f);
        float d2 = fmaxf(s2 + qn, 0.0f);
        float r0 = 1.0f / (d0 + 1e-8f);
        float r1 = 1.0f / (d1 + 1e-8f);
        float r2 = 1.0f / (d2 + 1e-8f);
        float inv = 1.0f / (r0 + r1 + r2);
        g_knn_idx[0][m] = g_ptid[i0];
        g_knn_idx[1][m] = g_ptid[i1];
        g_knn_idx[2][m] = g_ptid[i2];
        g_knn_w[0][m] = r0 * inv;
        g_knn_w[1][m] = r1 * inv;
        g_knn_w[2][m] = r2 * inv;
    }
}

// ---------------- fp32 linear: out[M][128] = A[M][KTOT] @ W[128][KTOT]^T + b ----
// FUSE also re-zeros the grid count arrays for the next replay.
template<int BM, int KTOT, bool FUSE>
__global__ void __launch_bounds__(BM*2) linear_kernel(
    const float* __restrict__ A,
    const float* __restrict__ W,
    const float* __restrict__ bias,
    float* __restrict__ out)
{
    constexpr int BK   = 32;
    constexpr int NT   = BM * 2;
    constexpr int ASTR = BM + 4;
    __shared__ __align__(16) float As[BK][ASTR];
    __shared__ __align__(16) float Ws[BK][C_OUT + 4];

    const int tid = threadIdx.x;
    const int tx  = tid & 15;
    const int ty  = tid >> 4;
    const int rowBase = blockIdx.x * BM;

    if (FUSE) {
        int g = blockIdx.x * NT + tid;
        if (g < NC) { g_cellcnt[g] = 0; g_qcnt[g] = 0; }
    }

    u64 acc[8][4];
    #pragma unroll
    for (int i = 0; i < 8; i++)
        #pragma unroll
        for (int j = 0; j < 4; j++) acc[i][j] = 0ull;

    for (int k0 = 0; k0 < KTOT; k0 += BK) {
        #pragma unroll
        for (int i = tid; i < BM * (BK/4); i += NT) {
            int r  = i >> 3;
            int kq = (i & 7) << 2;
            float4 v = *(const float4*)(A + (size_t)(rowBase + r) * KTOT + k0 + kq);
            As[kq+0][r] = v.x; As[kq+1][r] = v.y; As[kq+2][r] = v.z; As[kq+3][r] = v.w;
        }
        #pragma unroll
        for (int i = tid; i < C_OUT * (BK/4); i += NT) {
            int c  = i >> 3;
            int kq = (i & 7) << 2;
            float4 v = *(const float4*)(W + (size_t)c * KTOT + k0 + kq);
            Ws[kq+0][c] = v.x; Ws[kq+1][c] = v.y; Ws[kq+2][c] = v.z; Ws[kq+3][c] = v.w;
        }
        __syncthreads();
        #pragma unroll
        for (int k = 0; k < BK; k++) {
            float4 alo = *(const float4*)&As[k][ty*8];
            float4 ahi = *(const float4*)&As[k][ty*8 + 4];
            ulonglong2 w01 = *(const ulonglong2*)&Ws[k][tx*8];
            ulonglong2 w23 = *(const ulonglong2*)&Ws[k][tx*8 + 4];
            u64 wv[4] = {w01.x, w01.y, w23.x, w23.y};
            u64 a2[8];
            a2[0] = splat2(alo.x); a2[1] = splat2(alo.y);
            a2[2] = splat2(alo.z); a2[3] = splat2(alo.w);
            a2[4] = splat2(ahi.x); a2[5] = splat2(ahi.y);
            a2[6] = splat2(ahi.z); a2[7] = splat2(ahi.w);
            #pragma unroll
            for (int i = 0; i < 8; i++)
                #pragma unroll
                for (int j = 0; j < 4; j++)
                    fma2(acc[i][j], a2[i], wv[j]);
        }
        __syncthreads();
    }

    const int cb = tx * 8;
    float b[8];
    #pragma unroll
    for (int j = 0; j < 8; j++) b[j] = bias[cb + j];

    #pragma unroll
    for (int i = 0; i < 8; i++) {
        const int m = rowBase + ty*8 + i;
        float o[8];
        #pragma unroll
        for (int j = 0; j < 4; j++) {
            U64F2 cvt; cvt.u = acc[i][j];
            o[2*j]   = cvt.f.x + b[2*j];
            o[2*j+1] = cvt.f.y + b[2*j+1];
        }
        if (FUSE) {
            #pragma unroll
            for (int t = 0; t < 3; t++) {
                int   idx = g_knn_idx[t][m];
                float w   = g_knn_w[t][m];
                const float* fr = g_downf + (size_t)idx * C_OUT + cb;
                float4 glo = *(const float4*)fr;
                float4 ghi = *(const float4*)(fr + 4);
                o[0] = fmaf(w, glo.x, o[0]); o[1] = fmaf(w, glo.y, o[1]);
                o[2] = fmaf(w, glo.z, o[2]); o[3] = fmaf(w, glo.w, o[3]);
                o[4] = fmaf(w, ghi.x, o[4]); o[5] = fmaf(w, ghi.y, o[5]);
                o[6] = fmaf(w, ghi.z, o[6]); o[7] = fmaf(w, ghi.w, o[7]);
            }
        }
        *(float4*)(out + (size_t)m * C_OUT + cb)     = make_float4(o[0], o[1], o[2], o[3]);
        *(float4*)(out + (size_t)m * C_OUT + cb + 4) = make_float4(o[4], o[5], o[6], o[7]);
    }
}

// ---------------- launch (ncu profiles launch #4 = knn_grid) ----------------
extern "C" void kernel_launch(void* const* d_in, const int* in_sizes, int n_in,
                              void* d_out, int out_size) {
    (void)in_sizes; (void)n_in; (void)out_size;
    const float* up_points     = (const float*)d_in[0];
    const float* up_features   = (const float*)d_in[1];
    const float* down_points   = (const float*)d_in[2];
    const float* down_features = (const float*)d_in[3];
    const float* W_up          = (const float*)d_in[4];
    const float* b_up          = (const float*)d_in[5];
    const float* W_down        = (const float*)d_in[6];
    const float* b_down        = (const float*)d_in[7];
    float* out = (float*)d_out;

    float* downf_ptr = nullptr;
    cudaGetSymbolAddress((void**)&downf_ptr, g_downf);
    cudaFuncSetAttribute(scan_kernel, cudaFuncAttributeMaxDynamicSharedMemorySize,
                         SCAN_SMEM_BYTES);

    hist_kernel<<<(N_DOWN + M_UP + 255) / 256, 256>>>(down_points, up_points);      // 1
    scan_kernel<<<1, 1024, SCAN_SMEM_BYTES>>>();                                     // 2
    scatter_kernel<<<(N_DOWN + M_UP + 255) / 256, 256>>>(down_points, up_points);    // 3
    knn_grid_kernel<<<M_UP / QPB, 128>>>(up_points);                                 // 4 <- profiled
    linear_kernel<64, 256, false><<<N_DOWN / 64, 128>>>(down_features, W_down, b_down, downf_ptr); // 5
    linear_kernel<64, 128, true><<<M_UP / 64, 128>>>(up_features, W_up, b_up, out);  // 6
}

// round 12
// speedup vs baseline: 4.2095x; 1.1777x over previous
#include <cuda_runtime.h>
#include <stdint.h>

typedef unsigned long long u64;

#define M_UP   32768
#define N_DOWN 8192
#define C_OUT  128

#define GRID   32
#define NC     (GRID*GRID*GRID)
#define LOC    (-4.25f)
#define CELLH  (8.5f / GRID)
#define INVH   ((float)GRID / 8.5f)

#define SKEW(i) ((i) + ((i) >> 5))
#define SCAN_SMEM_INTS (SKEW(NC) + 32 + 1024)
#define SCAN_SMEM_BYTES (SCAN_SMEM_INTS * 4)

// ---------------- device scratch (no allocations allowed) ----------------
__device__ int   g_cellcnt[NC];        // zero-initialized at load; re-zeroed by lin_up
__device__ int   g_qcnt[NC];           // "
__device__ int   g_cellstart[NC + 1];
__device__ int   g_cellcur[NC];
__device__ int   g_qcur[NC];
__device__ __align__(16) float4 g_spts[N_DOWN];   // sorted points {x,y,z,|p|^2}
__device__ int   g_ptid[N_DOWN];                  // sorted pos -> original idx
__device__ int   g_qorder[M_UP];                  // sorted pos -> query idx
__device__ float g_downf[N_DOWN * C_OUT];
__device__ int   g_knn_idx[3][M_UP];
__device__ float g_knn_w[3][M_UP];

// ---------------- f32x2 helpers (sm_103a packed fp32) ----------------
__device__ __forceinline__ void fma2(u64& d, u64 a, u64 b) {
    asm("fma.rn.f32x2 %0, %1, %2, %0;" : "+l"(d) : "l"(a), "l"(b));
}
__device__ __forceinline__ u64 splat2(float s) {
    u64 d; unsigned int b = __float_as_uint(s);
    asm("mov.b64 %0, {%1, %1};" : "=l"(d) : "r"(b));
    return d;
}
union U64F2 { u64 u; float2 f; };

// ---------------- uniform grid helpers ----------------
__device__ __forceinline__ int clampi(int v, int lo, int hi) {
    return v < lo ? lo : (v > hi ? hi : v);
}
__device__ __forceinline__ int cell_coord(float x) {
    return clampi((int)floorf((x - LOC) * INVH), 0, GRID - 1);
}
__device__ __forceinline__ unsigned mexpand5(unsigned v) {
    v &= 0x1F;
    v = (v | (v << 8)) & 0x100F;
    v = (v | (v << 4)) & 0x10C3;
    v = (v | (v << 2)) & 0x1249;
    return v;
}
__device__ __forceinline__ int morton3(int x, int y, int z) {
    return (int)(mexpand5(x) | (mexpand5(y) << 1) | (mexpand5(z) << 2));
}

// branchless sorted top-3 insert (lane-local)
__device__ __forceinline__ void bins3(float s, int p,
                                      float& s0, float& s1, float& s2,
                                      int& i0, int& i1, int& i2) {
    bool b0 = s < s0, b1 = s < s1, b2 = s < s2;
    float ns2 = b1 ? s1 : (b2 ? s : s2);
    int   ni2 = b1 ? i1 : (b2 ? p : i2);
    float ns1 = b0 ? s0 : (b1 ? s : s1);
    int   ni1 = b0 ? i0 : (b1 ? p : i1);
    s0 = b0 ? s : s0;  i0 = b0 ? p : i0;
    s1 = ns1; i1 = ni1; s2 = ns2; i2 = ni2;
}

// ---------------- histogram ----------------
__global__ void hist_kernel(const float* __restrict__ dp,
                            const float* __restrict__ qp) {
    int i = blockIdx.x * blockDim.x + threadIdx.x;
    if (i < N_DOWN) {
        int cx = cell_coord(dp[3*i]), cy = cell_coord(dp[3*i+1]), cz = cell_coord(dp[3*i+2]);
        atomicAdd(&g_cellcnt[(cz * GRID + cy) * GRID + cx], 1);
    } else if (i < N_DOWN + M_UP) {
        int m = i - N_DOWN;
        int cx = cell_coord(qp[3*m]), cy = cell_coord(qp[3*m+1]), cz = cell_coord(qp[3*m+2]);
        atomicAdd(&g_qcnt[morton3(cx, cy, cz)], 1);
    }
}

// one block, 1024 threads: exclusive scan of both count arrays (coalesced staging)
__global__ void __launch_bounds__(1024) scan_kernel() {
    extern __shared__ int dsh[];
    int* tile = dsh;
    int* bsum = dsh + SKEW(NC) + 32;
    const int t = threadIdx.x;
    const int base = t * 32;

    #pragma unroll 1
    for (int pass = 0; pass < 2; pass++) {
        const int* src = pass ? g_qcnt : g_cellcnt;
        for (int j = t; j < NC; j += 1024) tile[SKEW(j)] = src[j];
        __syncthreads();

        int loc[32]; int s = 0;
        #pragma unroll
        for (int i = 0; i < 32; i++) { loc[i] = s; s += tile[SKEW(base + i)]; }
        bsum[t] = s;
        __syncthreads();
        for (int d = 1; d < 1024; d <<= 1) {
            int a = (t >= d) ? bsum[t - d] : 0;
            __syncthreads();
            bsum[t] += a;
            __syncthreads();
        }
        int off = bsum[t] - s;
        #pragma unroll
        for (int i = 0; i < 32; i++) tile[SKEW(base + i)] = off + loc[i];
        __syncthreads();

        if (pass == 0) {
            for (int j = t; j < NC; j += 1024) {
                int v = tile[SKEW(j)];
                g_cellstart[j] = v;
                g_cellcur[j]   = v;
            }
            if (t == 1023) g_cellstart[NC] = off + s;
        } else {
            for (int j = t; j < NC; j += 1024) g_qcur[j] = tile[SKEW(j)];
        }
        __syncthreads();
    }
}

__global__ void scatter_kernel(const float* __restrict__ dp,
                               const float* __restrict__ qp) {
    int i = blockIdx.x * blockDim.x + threadIdx.x;
    if (i < N_DOWN) {
        float x = dp[3*i], y = dp[3*i+1], z = dp[3*i+2];
        int cx = cell_coord(x), cy = cell_coord(y), cz = cell_coord(z);
        int pos = atomicAdd(&g_cellcur[(cz * GRID + cy) * GRID + cx], 1);
        g_spts[pos] = make_float4(x, y, z, fmaf(x, x, fmaf(y, y, z * z)));
        g_ptid[pos] = i;
    } else if (i < N_DOWN + M_UP) {
        int m = i - N_DOWN;
        int cx = cell_coord(qp[3*m]), cy = cell_coord(qp[3*m+1]), cz = cell_coord(qp[3*m+2]);
        int pos = atomicAdd(&g_qcur[morton3(cx, cy, cz)], 1);
        g_qorder[pos] = m;
    }
}

// ---------------- exact KNN: one warp per query ----------------
// Lanes process shell cells in parallel; exact global top-3 via 3-round
// k-way heads extraction (shfl argmin with (s,idx) tie-break) that also
// serves as the ring stop bound and the final merge.

// Extract global top-3 from the 32 sorted lane lists; clears dominated
// remainders (lane 0 keeps the global 3). Returns gs/gi on ALL lanes.
__device__ __forceinline__ void extract3(int lane,
        float& s0, float& s1, float& s2, int& i0, int& i1, int& i2,
        float& gs0, float& gs1, float& gs2, int& gi0, int& gi1, int& gi2) {
    float g[3]; int gi[3];
    #pragma unroll
    for (int k = 0; k < 3; k++) {
        float bs = s0; int bi = i0;
        #pragma unroll
        for (int off = 16; off; off >>= 1) {
            float os = __shfl_xor_sync(0xFFFFFFFFu, bs, off);
            int   oi = __shfl_xor_sync(0xFFFFFFFFu, bi, off);
            bool take = (os < bs) || (os == bs && oi < bi);
            bs = take ? os : bs; bi = take ? oi : bi;
        }
        if (s0 == bs && i0 == bi) {       // owner pops its head
            s0 = s1; i0 = i1; s1 = s2; i1 = i2; s2 = 3e38f; i2 = 0;
        }
        g[k] = bs; gi[k] = bi;
    }
    // reset: lane 0 carries the global 3; all other entries are dominated
    bool l0 = (lane == 0);
    s0 = l0 ? g[0] : 3e38f;  i0 = l0 ? gi[0] : 0;
    s1 = l0 ? g[1] : 3e38f;  i1 = l0 ? gi[1] : 0;
    s2 = l0 ? g[2] : 3e38f;  i2 = l0 ? gi[2] : 0;
    gs0 = g[0]; gs1 = g[1]; gs2 = g[2];
    gi0 = gi[0]; gi1 = gi[1]; gi2 = gi[2];
}

__global__ void __launch_bounds__(256) knn_warp_kernel(const float* __restrict__ qp) {
    const int lane = threadIdx.x & 31;
    const int wid  = (blockIdx.x * blockDim.x + threadIdx.x) >> 5;  // query slot
    const int m = g_qorder[wid];

    const float qx = qp[3*m], qy = qp[3*m+1], qz = qp[3*m+2];
    const float qn = fmaf(qx, qx, fmaf(qy, qy, qz * qz));

    const int cx = cell_coord(qx), cy = cell_coord(qy), cz = cell_coord(qz);
    const float fx = qx - (LOC + cx * CELLH);
    const float fy = qy - (LOC + cy * CELLH);
    const float fz = qz - (LOC + cz * CELLH);
    const float gm = fmaxf(fmaxf(fmaxf(fx, CELLH - fx), fmaxf(fy, CELLH - fy)),
                           fmaxf(fz, CELLH - fz));

    float s0 = 3e38f, s1 = 3e38f, s2 = 3e38f;   // lane-local sorted top-3
    int   i0 = 0,     i1 = 0,     i2 = 0;       // (s = d^2 - qn)
    float gs0 = 3e38f, gs1 = 3e38f, gs2 = 3e38f;
    int   gi0 = 0,     gi1 = 0,    gi2 = 0;

    // ---- R = 0: home cell, points lane-strided ----
    {
        const int cell = (cz * GRID + cy) * GRID + cx;
        const int st = g_cellstart[cell], en = g_cellstart[cell + 1];
        for (int p = st + lane; p < en; p += 32) {
            float4 P = g_spts[p];
            float s = fmaf(-2.0f, fmaf(qx, P.x, fmaf(qy, P.y, qz * P.z)), P.w);
            if (s < s2) bins3(s, p, s0, s1, s2, i0, i1, i2);
        }
        float mind = CELLH - gm;
        if (mind > 0.0f) {
            extract3(lane, s0, s1, s2, i0, i1, i2, gs0, gs1, gs2, gi0, gi1, gi2);
            if (fmaf(mind, mind, -qn) >= gs2) goto done;
        }
    }

    // ---- rings R >= 1: shell cells lane-strided via 6-face decode ----
    for (int R = 1; R < GRID; R++) {
        const int w1 = 2 * R + 1, w0 = w1 - 2;
        const int nA = w1 * w1, nC = w0 * w1, nE = w0 * w0;
        const int nAB = 2 * nA, nABC2 = nAB + 2 * nC;
        const int total = nABC2 + 2 * nE;
        const float rw1 = 1.0f / (float)w1, rw0 = 1.0f / (float)w0;

        for (int pi = lane; pi < total; pi += 32) {
            int dx, dy, dz;
            if (pi < nAB) {                    // z = +-R faces (w1 x w1)
                int u = pi; dz = R; if (u >= nA) { u -= nA; dz = -R; }
                int qd = (int)(((float)u + 0.5f) * rw1);
                dy = qd - R; dx = (u - qd * w1) - R;
            } else if (pi < nABC2) {           // y = +-R faces (w0 z x w1 x)
                int u = pi - nAB; dy = R; if (u >= nC) { u -= nC; dy = -R; }
                int qd = (int)(((float)u + 0.5f) * rw1);
                dz = qd - (R - 1); dx = (u - qd * w1) - R;
            } else {                           // x = +-R faces (w0 x w0)
                int u = pi - nABC2; dx = R; if (u >= nE) { u -= nE; dx = -R; }
                int qd = (int)(((float)u + 0.5f) * rw0);
                dz = qd - (R - 1); dy = (u - qd * w0) - (R - 1);
            }
            int x = cx + dx, y = cy + dy, z = cz + dz;
            if (((unsigned)x | (unsigned)y | (unsigned)z) >= (unsigned)GRID) continue;
            const int cell = (z * GRID + y) * GRID + x;
            const int st = g_cellstart[cell], en = g_cellstart[cell + 1];
            for (int p = st; p < en; p++) {
                float4 P = g_spts[p];
                float s = fmaf(-2.0f, fmaf(qx, P.x, fmaf(qy, P.y, qz * P.z)), P.w);
                if (s < s2) bins3(s, p, s0, s1, s2, i0, i1, i2);
            }
        }
        // exact stop: global 3rd-best from full extraction (also merges)
        float mind = (float)(R + 1) * CELLH - gm;   // > 0 for R >= 1
        extract3(lane, s0, s1, s2, i0, i1, i2, gs0, gs1, gs2, gi0, gi1, gi2);
        if (fmaf(mind, mind, -qn) >= gs2) break;
    }

done:
    if (lane == 0) {
        float d0 = fmaxf(gs0 + qn, 0.0f);
        float d1 = fmaxf(gs1 + qn, 0.0f);
        float d2 = fmaxf(gs2 + qn, 0.0f);
        float r0 = 1.0f / (d0 + 1e-8f);
        float r1 = 1.0f / (d1 + 1e-8f);
        float r2 = 1.0f / (d2 + 1e-8f);
        float inv = 1.0f / (r0 + r1 + r2);
        g_knn_idx[0][m] = g_ptid[gi0];
        g_knn_idx[1][m] = g_ptid[gi1];
        g_knn_idx[2][m] = g_ptid[gi2];
        g_knn_w[0][m] = r0 * inv;
        g_knn_w[1][m] = r1 * inv;
        g_knn_w[2][m] = r2 * inv;
    }
}

// ---------------- fp32 linear: out[M][128] = A[M][KTOT] @ W[128][KTOT]^T + b ----
// FUSE also re-zeros the grid count arrays for the next replay.
template<int BM, int KTOT, bool FUSE>
__global__ void __launch_bounds__(BM*2) linear_kernel(
    const float* __restrict__ A,
    const float* __restrict__ W,
    const float* __restrict__ bias,
    float* __restrict__ out)
{
    constexpr int BK   = 32;
    constexpr int NT   = BM * 2;
    constexpr int ASTR = BM + 4;
    __shared__ __align__(16) float As[BK][ASTR];
    __shared__ __align__(16) float Ws[BK][C_OUT + 4];

    const int tid = threadIdx.x;
    const int tx  = tid & 15;
    const int ty  = tid >> 4;
    const int rowBase = blockIdx.x * BM;

    if (FUSE) {
        int g = blockIdx.x * NT + tid;
        if (g < NC) { g_cellcnt[g] = 0; g_qcnt[g] = 0; }
    }

    u64 acc[8][4];
    #pragma unroll
    for (int i = 0; i < 8; i++)
        #pragma unroll
        for (int j = 0; j < 4; j++) acc[i][j] = 0ull;

    for (int k0 = 0; k0 < KTOT; k0 += BK) {
        #pragma unroll
        for (int i = tid; i < BM * (BK/4); i += NT) {
            int r  = i >> 3;
            int kq = (i & 7) << 2;
            float4 v = *(const float4*)(A + (size_t)(rowBase + r) * KTOT + k0 + kq);
            As[kq+0][r] = v.x; As[kq+1][r] = v.y; As[kq+2][r] = v.z; As[kq+3][r] = v.w;
        }
        #pragma unroll
        for (int i = tid; i < C_OUT * (BK/4); i += NT) {
            int c  = i >> 3;
            int kq = (i & 7) << 2;
            float4 v = *(const float4*)(W + (size_t)c * KTOT + k0 + kq);
            Ws[kq+0][c] = v.x; Ws[kq+1][c] = v.y; Ws[kq+2][c] = v.z; Ws[kq+3][c] = v.w;
        }
        __syncthreads();
        #pragma unroll
        for (int k = 0; k < BK; k++) {
            float4 alo = *(const float4*)&As[k][ty*8];
            float4 ahi = *(const float4*)&As[k][ty*8 + 4];
            ulonglong2 w01 = *(const ulonglong2*)&Ws[k][tx*8];
            ulonglong2 w23 = *(const ulonglong2*)&Ws[k][tx*8 + 4];
            u64 wv[4] = {w01.x, w01.y, w23.x, w23.y};
            u64 a2[8];
            a2[0] = splat2(alo.x); a2[1] = splat2(alo.y);
            a2[2] = splat2(alo.z); a2[3] = splat2(alo.w);
            a2[4] = splat2(ahi.x); a2[5] = splat2(ahi.y);
            a2[6] = splat2(ahi.z); a2[7] = splat2(ahi.w);
            #pragma unroll
            for (int i = 0; i < 8; i++)
                #pragma unroll
                for (int j = 0; j < 4; j++)
                    fma2(acc[i][j], a2[i], wv[j]);
        }
        __syncthreads();
    }

    const int cb = tx * 8;
    float b[8];
    #pragma unroll
    for (int j = 0; j < 8; j++) b[j] = bias[cb + j];

    #pragma unroll
    for (int i = 0; i < 8; i++) {
        const int m = rowBase + ty*8 + i;
        float o[8];
        #pragma unroll
        for (int j = 0; j < 4; j++) {
            U64F2 cvt; cvt.u = acc[i][j];
            o[2*j]   = cvt.f.x + b[2*j];
            o[2*j+1] = cvt.f.y + b[2*j+1];
        }
        if (FUSE) {
            #pragma unroll
            for (int t = 0; t < 3; t++) {
                int   idx = g_knn_idx[t][m];
                float w   = g_knn_w[t][m];
                const float* fr = g_downf + (size_t)idx * C_OUT + cb;
                float4 glo = *(const float4*)fr;
                float4 ghi = *(const float4*)(fr + 4);
                o[0] = fmaf(w, glo.x, o[0]); o[1] = fmaf(w, glo.y, o[1]);
                o[2] = fmaf(w, glo.z, o[2]); o[3] = fmaf(w, glo.w, o[3]);
                o[4] = fmaf(w, ghi.x, o[4]); o[5] = fmaf(w, ghi.y, o[5]);
                o[6] = fmaf(w, ghi.z, o[6]); o[7] = fmaf(w, ghi.w, o[7]);
            }
        }
        *(float4*)(out + (size_t)m * C_OUT + cb)     = make_float4(o[0], o[1], o[2], o[3]);
        *(float4*)(out + (size_t)m * C_OUT + cb + 4) = make_float4(o[4], o[5], o[6], o[7]);
    }
}

// ---------------- launch (ncu profiles launch #4 = knn_warp) ----------------
extern "C" void kernel_launch(void* const* d_in, const int* in_sizes, int n_in,
                              void* d_out, int out_size) {
    (void)in_sizes; (void)n_in; (void)out_size;
    const float* up_points     = (const float*)d_in[0];
    const float* up_features   = (const float*)d_in[1];
    const float* down_points   = (const float*)d_in[2];
    const float* down_features = (const float*)d_in[3];
    const float* W_up          = (const float*)d_in[4];
    const float* b_up          = (const float*)d_in[5];
    const float* W_down        = (const float*)d_in[6];
    const float* b_down        = (const float*)d_in[7];
    float* out = (float*)d_out;

    float* downf_ptr = nullptr;
    cudaGetSymbolAddress((void**)&downf_ptr, g_downf);
    cudaFuncSetAttribute(scan_kernel, cudaFuncAttributeMaxDynamicSharedMemorySize,
                         SCAN_SMEM_BYTES);

    hist_kernel<<<(N_DOWN + M_UP + 255) / 256, 256>>>(down_points, up_points);      // 1
    scan_kernel<<<1, 1024, SCAN_SMEM_BYTES>>>();                                     // 2
    scatter_kernel<<<(N_DOWN + M_UP + 255) / 256, 256>>>(down_points, up_points);    // 3
    knn_warp_kernel<<<M_UP / 8, 256>>>(up_points);                                   // 4 <- profiled
    linear_kernel<64, 256, false><<<N_DOWN / 64, 128>>>(down_features, W_down, b_down, downf_ptr); // 5
    linear_kernel<64, 128, true><<<M_UP / 64, 128>>>(up_features, W_up, b_up, out);  // 6
}